// round 12
// baseline (speedup 1.0000x reference)
#include <cuda_runtime.h>
#include <cstdint>

// Dynamic 5x5 per-pixel convolution + leaky_relu(0.2), replicate padding.
// x:      (N, C, H, W)    f32  -> 8 MB   (staged per CTA via cp.async.16B)
// kernel: (N, C*25, H, W) f32  -> 200 MB (dominant HBM stream, read once)
// out:    (N, C, H, W)    f32  -> 8 MB
//
// R10 = R8 + seamless row-boundary prefetch: each row's k1==4 slot prefetches
// the NEXT row's k1=0 taps. Buffer parity is a compile-time template param
// (rows flip parity since 5 taps/row is odd); rr-loop unrolled by 2 so both
// parities are static without R7's full 20-row flatten.

#define W_DIM 256
#define H_DIM 256
#define HW (W_DIM * H_DIM)
#define KS 5
#define PAD 2
#define ROWS_PER_CTA 16
#define ROWS_PER_THREAD 4
#define TILE_ROWS (ROWS_PER_CTA + 2 * PAD)   // 20
#define SROW 272                             // 16B-aligned row stride
#define COL0 4                               // smem col = gx + COL0
#define NTHREADS 256

__device__ __forceinline__ void cp_async16(uint32_t smem_addr, const float* gptr) {
    asm volatile("cp.async.cg.shared.global [%0], [%1], 16;"
                 :: "r"(smem_addr), "l"(gptr));
}
__device__ __forceinline__ void cp_async4(uint32_t smem_addr, const float* gptr) {
    asm volatile("cp.async.ca.shared.global [%0], [%1], 4;"
                 :: "r"(smem_addr), "l"(gptr));
}

// One output row (4 px). Consumes this row's k1=0 taps from kv[P] (caller /
// previous row preloaded them). Double-buffers within the row; at k1==4
// prefetches next row's k1=0 taps into kv[P^1] when do_next.
template<int P>
__device__ __forceinline__ void conv_row(
    const float xs[TILE_ROWS][SROW], int hloc, int wbase,
    const float* kbase, const float* nkbase, bool do_next,
    float4 kv[2][KS], float* optr)
{
    float acc0 = 0.f, acc1 = 0.f, acc2 = 0.f, acc3 = 0.f;

    #pragma unroll
    for (int k1 = 0; k1 < KS; k1++) {
        const int cur = (k1 & 1) ^ P;
        if (k1 < KS - 1) {
            #pragma unroll
            for (int k2 = 0; k2 < KS; k2++)
                kv[cur ^ 1][k2] = __ldcs((const float4*)(
                    kbase + (size_t)((k1 + 1) * KS + k2) * HW));
        } else if (do_next) {
            #pragma unroll
            for (int k2 = 0; k2 < KS; k2++)
                kv[cur ^ 1][k2] = __ldcs((const float4*)(
                    nkbase + (size_t)k2 * HW));
        }

        // 12-float window (3 aligned LDS.128); taps use arr[k2+2+i]
        float4 a = *(const float4*)&xs[hloc + k1][wbase];
        float4 b = *(const float4*)&xs[hloc + k1][wbase + 4];
        float4 c = *(const float4*)&xs[hloc + k1][wbase + 8];
        float arr[12] = {a.x, a.y, a.z, a.w, b.x, b.y, b.z, b.w,
                         c.x, c.y, c.z, c.w};

        #pragma unroll
        for (int k2 = 0; k2 < KS; k2++) {
            float4 c4 = kv[cur][k2];
            acc0 = fmaf(c4.x, arr[k2 + 2], acc0);
            acc1 = fmaf(c4.y, arr[k2 + 3], acc1);
            acc2 = fmaf(c4.z, arr[k2 + 4], acc2);
            acc3 = fmaf(c4.w, arr[k2 + 5], acc3);
        }
    }

    acc0 = acc0 >= 0.f ? acc0 : 0.2f * acc0;
    acc1 = acc1 >= 0.f ? acc1 : 0.2f * acc1;
    acc2 = acc2 >= 0.f ? acc2 : 0.2f * acc2;
    acc3 = acc3 >= 0.f ? acc3 : 0.2f * acc3;
    __stcs((float4*)optr, make_float4(acc0, acc1, acc2, acc3));
}

__global__ __launch_bounds__(NTHREADS, 4)
void dynconv5x5_kernel(const float* __restrict__ x,
                       const float* __restrict__ kern,
                       float* __restrict__ out)
{
    __shared__ float xs[TILE_ROWS][SROW];

    const int nc    = blockIdx.x >> 4;                   // plane index (0..31)
    const int hbase = (blockIdx.x & 15) * ROWS_PER_CTA;  // strip start row
    const int tx    = threadIdx.x;                       // 0..63 -> 4-px group
    const int ty    = threadIdx.y;                       // 0..3
    const int tid   = ty * 64 + tx;
    const int wbase = tx * 4;

    const float* xp    = x    + (size_t)nc * HW;
    const float* kpl   = kern + (size_t)nc * 25 * HW;
    float*       outpl = out  + (size_t)nc * HW;

    uint32_t xs_base;
    asm("{ .reg .u64 t; cvta.to.shared.u64 t, %1; cvt.u32.u64 %0, t; }"
        : "=r"(xs_base) : "l"(&xs[0][0]));

    // ---- stage interior: 20 rows x 64 aligned float4 groups (16B cp.async) ----
    for (int i = tid; i < TILE_ROWS * (W_DIM / 4); i += NTHREADS) {
        int r = i >> 6;                 // row 0..19
        int g = i & 63;                 // float4 group, gx = 4g
        int gy = hbase + r - PAD;
        gy = gy < 0 ? 0 : (gy > H_DIM - 1 ? H_DIM - 1 : gy);
        cp_async16(xs_base + (uint32_t)(r * SROW + COL0 + 4 * g) * 4u,
                   xp + gy * W_DIM + 4 * g);
    }
    // ---- stage edges: 4 clamped scalars per row ----
    for (int i = tid; i < TILE_ROWS * 4; i += NTHREADS) {
        int r = i >> 2;
        int e = i & 3;
        int gy = hbase + r - PAD;
        gy = gy < 0 ? 0 : (gy > H_DIM - 1 ? H_DIM - 1 : gy);
        int col = (e < 2) ? (2 + e) : (258 + e);          // 2,3,260,261
        int gx  = (e < 2) ? 0 : (W_DIM - 1);
        cp_async4(xs_base + (uint32_t)(r * SROW + col) * 4u,
                  xp + gy * W_DIM + gx);
    }
    asm volatile("cp.async.commit_group;");

    // ---- prefetch rr=0 row's k1=0 taps into kv[0] BEFORE the stage wait ----
    const float* kb = kpl + (size_t)(hbase + ty) * W_DIM + wbase; // rr=0 base
    float*       ob = outpl + (size_t)(hbase + ty) * W_DIM + wbase;

    float4 kv[2][KS];
    #pragma unroll
    for (int k2 = 0; k2 < KS; k2++)
        kv[0][k2] = __ldcs((const float4*)(kb + (size_t)k2 * HW));

    asm volatile("cp.async.wait_group 0;");
    __syncthreads();   // the ONLY barrier

    // rows: hloc = ty + 4*rr. Parity alternates 0,1,0,1; unroll-by-2 keeps it
    // static. Each row hands the next row's k1=0 taps over via kv[P^1].
    #pragma unroll 1
    for (int r0 = 0; r0 < ROWS_PER_THREAD; r0 += 2) {
        const float* kb0 = kb + (size_t)(r0 * 4) * W_DIM;
        const float* kb1 = kb0 + (size_t)4 * W_DIM;
        const float* kb2 = kb1 + (size_t)4 * W_DIM;   // may be OOB; never loaded then
        float* ob0 = ob + (size_t)(r0 * 4) * W_DIM;
        float* ob1 = ob0 + (size_t)4 * W_DIM;

        conv_row<0>(xs, ty + r0 * 4,     wbase, kb0, kb1, true,       kv, ob0);
        conv_row<1>(xs, ty + r0 * 4 + 4, wbase, kb1, kb2, r0 + 2 < ROWS_PER_THREAD,
                    kv, ob1);
    }
}

extern "C" void kernel_launch(void* const* d_in, const int* in_sizes, int n_in,
                              void* d_out, int out_size)
{
    const float* x    = (const float*)d_in[0];
    const float* kern = (const float*)d_in[1];
    float* out        = (float*)d_out;

    const int NC = in_sizes[0] / HW;              // 32 for (4,8,256,256)

    dim3 block(64, 4);
    dim3 grid(NC * (H_DIM / ROWS_PER_CTA));       // 512 CTAs, single wave
    dynconv5x5_kernel<<<grid, block>>>(x, kern, out);
}